// round 4
// baseline (speedup 1.0000x reference)
#include <cuda_runtime.h>
#include <cstdint>

// ============================================================================
// q[2,32,2048,128], k[2,32,2048,128], v[2,32,2048,128] fp32,
// mask[2,1,2048,2048] bool (delivered as uint8/int32/float32 - detected),
// out[2,32,2048,128] fp32.
// compute_103 virtual arch -> no tcgen05; tensor pipe via mma.sync tf32.
// ============================================================================
#define BATCH 2
#define NHEAD 32
#define BN    64
#define TSEQ  2048
#define SSEQ  2048
#define HDIM  128
#define TILE  128
#define NSTILE 16
#define SCALE_F 0.08838834764831845f   // 1/sqrt(128)
#define PAD   132                      // smem row stride in floats

#define MASK_ELEMS ((size_t)BATCH * TSEQ * SSEQ)

// Scratch: RNA-rounded K, RNA-rounded transposed V ([bn][h][s]), canonical mask
__device__ float   g_k [(size_t)BN * SSEQ * HDIM];
__device__ float   g_vt[(size_t)BN * HDIM * SSEQ];
__device__ uint8_t g_mask[MASK_ELEMS];
__device__ int     g_mask_kind;   // 0=uint8, 1=int32, 2=float32

// ============================================================================
// helpers
// ============================================================================
__device__ __forceinline__ float rna_tf32(float x) {
    uint32_t r;
    asm("cvt.rna.tf32.f32 %0, %1;" : "=r"(r) : "f"(x));
    return __uint_as_float(r);
}
__device__ __forceinline__ uint32_t smem_to_u32(const void* p) {
    uint32_t a;
    asm("{ .reg .u64 t; cvta.to.shared.u64 t, %1; cvt.u32.u64 %0, t; }"
        : "=r"(a) : "l"(p));
    return a;
}
__device__ __forceinline__ void cp_async16(uint32_t dst, const void* src) {
    asm volatile("cp.async.cg.shared.global [%0], [%1], 16;"
                 :: "r"(dst), "l"(src) : "memory");
}
#define CP_COMMIT() asm volatile("cp.async.commit_group;" ::: "memory")
#define CP_WAIT0()  asm volatile("cp.async.wait_group 0;"  ::: "memory")

// D += A(16x8,row) * B(8x8,col), tf32
__device__ __forceinline__ void mma_tf32(float* d, const uint32_t* a,
                                         uint32_t b0, uint32_t b1) {
    asm volatile(
        "mma.sync.aligned.m16n8k8.row.col.f32.tf32.tf32.f32 "
        "{%0,%1,%2,%3}, {%4,%5,%6,%7}, {%8,%9}, {%0,%1,%2,%3};"
        : "+f"(d[0]), "+f"(d[1]), "+f"(d[2]), "+f"(d[3])
        : "r"(a[0]), "r"(a[1]), "r"(a[2]), "r"(a[3]), "r"(b0), "r"(b1));
}

// ============================================================================
// Mask dtype detection + canonicalization
// ============================================================================
#define DET_WORDS 65536
__global__ void mask_detect_kernel(const uint32_t* __restrict__ m) {
    __shared__ int s_not01, s_notf32;
    if (threadIdx.x == 0) { s_not01 = 0; s_notf32 = 0; }
    __syncthreads();
    int not01 = 0, notf32 = 0;
    for (int i = threadIdx.x; i < DET_WORDS; i += blockDim.x) {
        uint32_t w = m[i];
        if (w != 0u && w != 1u) not01 = 1;
        if (w != 0u && w != 0x3F800000u) notf32 = 1;
    }
    if (not01)  atomicOr(&s_not01, 1);
    if (notf32) atomicOr(&s_notf32, 1);
    __syncthreads();
    if (threadIdx.x == 0) {
        int kind;
        if (!s_not01)       kind = 1;   // int32 0/1
        else if (!s_notf32) kind = 2;   // float32 0.0/1.0
        else                kind = 0;   // packed uint8
        g_mask_kind = kind;
    }
}

__global__ void mask_convert_kernel(const void* __restrict__ m) {
    size_t i = (size_t)blockIdx.x * blockDim.x + threadIdx.x;
    if (i >= MASK_ELEMS) return;
    int kind = g_mask_kind;
    uint8_t v;
    if (kind == 1)      v = (((const int*)m)[i] != 0) ? 1 : 0;
    else if (kind == 2) v = (((const float*)m)[i] != 0.0f) ? 1 : 0;
    else                v = (((const uint8_t*)m)[i] != 0) ? 1 : 0;
    g_mask[i] = v;
}

// ============================================================================
// Prep kernels: RNA-round K; transpose+RNA-round V
// ============================================================================
__global__ void prep_k_kernel(const float* __restrict__ k) {
    size_t i = (size_t)blockIdx.x * blockDim.x + threadIdx.x;
    float4 v = ((const float4*)k)[i];
    v.x = rna_tf32(v.x); v.y = rna_tf32(v.y);
    v.z = rna_tf32(v.z); v.w = rna_tf32(v.w);
    ((float4*)g_k)[i] = v;
}

__global__ void vT_kernel(const float* __restrict__ v) {
    __shared__ float tile[32][33];
    int bn = blockIdx.z;
    const float* vp = v + (size_t)bn * SSEQ * HDIM;
    float* vtp = g_vt + (size_t)bn * HDIM * SSEQ;
    int s0 = blockIdx.x * 32, h0 = blockIdx.y * 32;
    #pragma unroll
    for (int dy = threadIdx.y; dy < 32; dy += 8)
        tile[dy][threadIdx.x] = rna_tf32(vp[(size_t)(s0 + dy) * HDIM + h0 + threadIdx.x]);
    __syncthreads();
    #pragma unroll
    for (int dy = threadIdx.y; dy < 32; dy += 8)
        vtp[(size_t)(h0 + dy) * SSEQ + s0 + threadIdx.x] = tile[threadIdx.x][dy];
}

// ============================================================================
// Main attention kernel. Grid (TSEQ/128, BN), 256 threads, 1 CTA/SM.
// SMEM: sK[128][132], sV[128][132] (V^T: rows=h, cols=s), sP[128][132].
// ============================================================================
#define SM_K 0
#define SM_V (128 * PAD)
#define SM_P (256 * PAD)
#define SMEM_FLOATS (384 * PAD)
#define SMEM_BYTES  (SMEM_FLOATS * 4)

__global__ void __launch_bounds__(256, 1)
attn_kernel(const float* __restrict__ q, float* __restrict__ out) {
    extern __shared__ float sm[];
    float* sK = sm + SM_K;
    float* sV = sm + SM_V;
    float* sP = sm + SM_P;
    const uint32_t sK_u = smem_to_u32(sK);
    const uint32_t sV_u = smem_to_u32(sV);

    const int tid = threadIdx.x;
    const int w = tid >> 5, l = tid & 31;
    const int lr = l >> 2, lc = l & 3;
    const int bn = blockIdx.y;
    const int t0 = blockIdx.x * TILE;
    const int b = bn >> 5;               // NHEAD == 32
    const int row0 = w * 16 + lr;        // local row of c0/c1 (c2/c3 at +8)

    // ---- stage Q tile (scale folded + RNA) into sP, then load A-frags ----
    const float* gq = q + ((size_t)bn * TSEQ + t0) * HDIM;
    #pragma unroll
    for (int ch = 0; ch < 16; ch++) {
        int idx = tid + ch * 256;
        int r = idx >> 5, c4 = idx & 31;
        float4 v = *(const float4*)(gq + r * HDIM + c4 * 4);
        v.x = rna_tf32(v.x * SCALE_F); v.y = rna_tf32(v.y * SCALE_F);
        v.z = rna_tf32(v.z * SCALE_F); v.w = rna_tf32(v.w * SCALE_F);
        *(float4*)(sP + r * PAD + c4 * 4) = v;
    }
    __syncthreads();

    uint32_t qa[16][4];
    #pragma unroll
    for (int kk = 0; kk < 16; kk++) {
        const float* p = sP + row0 * PAD + kk * 8 + lc;
        qa[kk][0] = __float_as_uint(p[0]);
        qa[kk][1] = __float_as_uint(p[8 * PAD]);
        qa[kk][2] = __float_as_uint(p[4]);
        qa[kk][3] = __float_as_uint(p[8 * PAD + 4]);
    }

    float o[16][4];
    #pragma unroll
    for (int nb = 0; nb < 16; nb++) {
        o[nb][0] = 0.f; o[nb][1] = 0.f; o[nb][2] = 0.f; o[nb][3] = 0.f;
    }
    float dsum0 = 0.f, dsum1 = 0.f;

    const float* gk = g_k + (size_t)bn * SSEQ * HDIM;
    const float* gv = g_vt + (size_t)bn * HDIM * SSEQ;
    const uint8_t* gm0 = g_mask + (size_t)b * TSEQ * SSEQ
                       + (size_t)(t0 + row0) * SSEQ + 2 * lc;
    const uint8_t* gm1 = gm0 + (size_t)8 * SSEQ;

    for (int i = 0; i < NSTILE; i++) {
        if (i) __syncthreads();          // everyone done reading sK/sV
        // ---- cp.async K tile [s][h] and V^T tile [h][s-segment] ----
        const float* gki = gk + (size_t)i * TILE * HDIM;
        const float* gvi = gv + i * TILE;
        #pragma unroll
        for (int ch = 0; ch < 16; ch++) {
            int idx = tid + ch * 256;
            int r = idx >> 5, c4 = idx & 31;
            cp_async16(sK_u + (uint32_t)(r * PAD + c4 * 4) * 4,
                       gki + r * HDIM + c4 * 4);
        }
        #pragma unroll
        for (int ch = 0; ch < 16; ch++) {
            int idx = tid + ch * 256;
            int r = idx >> 5, c4 = idx & 31;
            cp_async16(sV_u + (uint32_t)(r * PAD + c4 * 4) * 4,
                       gvi + (size_t)r * SSEQ + c4 * 4);
        }
        CP_COMMIT();
        CP_WAIT0();
        __syncthreads();

        // ---- S = Q @ K^T : c[nb] accumulates 16x8 blocks, n = s-col ----
        float c[16][4];
        #pragma unroll
        for (int nb = 0; nb < 16; nb++) {
            c[nb][0] = 0.f; c[nb][1] = 0.f; c[nb][2] = 0.f; c[nb][3] = 0.f;
        }
        #pragma unroll
        for (int kk = 0; kk < 16; kk++) {
            const float* bp = sK + lr * PAD + kk * 8 + lc;  // row = nb*8+lr, col h
            #pragma unroll
            for (int nb = 0; nb < 16; nb++) {
                uint32_t b0 = __float_as_uint(bp[nb * 8 * PAD]);
                uint32_t b1 = __float_as_uint(bp[nb * 8 * PAD + 4]);
                mma_tf32(c[nb], qa[kk], b0, b1);
            }
        }

        // ---- P = mask ? exp(S) : 0 ; accumulate denom ; P -> sP ----
        const uint8_t* m0p = gm0 + i * TILE;
        const uint8_t* m1p = gm1 + i * TILE;
        #pragma unroll
        for (int nb = 0; nb < 16; nb++) {
            uchar2 m0 = *(const uchar2*)(m0p + nb * 8);
            uchar2 m1 = *(const uchar2*)(m1p + nb * 8);
            float p0 = m0.x ? rna_tf32(__expf(c[nb][0])) : 0.f;
            float p1 = m0.y ? rna_tf32(__expf(c[nb][1])) : 0.f;
            float p2 = m1.x ? rna_tf32(__expf(c[nb][2])) : 0.f;
            float p3 = m1.y ? rna_tf32(__expf(c[nb][3])) : 0.f;
            dsum0 += p0 + p1;
            dsum1 += p2 + p3;
            *(float2*)(sP + row0 * PAD + nb * 8 + 2 * lc)       = make_float2(p0, p1);
            *(float2*)(sP + (row0 + 8) * PAD + nb * 8 + 2 * lc) = make_float2(p2, p3);
        }
        __syncwarp();   // P rows are warp-private; order STS -> LDS in-warp

        // ---- O += P @ V : A = P (own rows), B = V^T frags, n = h-col ----
        #pragma unroll
        for (int kk = 0; kk < 16; kk++) {
            uint32_t pa[4];
            const float* pp = sP + row0 * PAD + kk * 8 + lc;
            pa[0] = __float_as_uint(pp[0]);
            pa[1] = __float_as_uint(pp[8 * PAD]);
            pa[2] = __float_as_uint(pp[4]);
            pa[3] = __float_as_uint(pp[8 * PAD + 4]);
            const float* bp = sV + lr * PAD + kk * 8 + lc;  // row = h = nb*8+lr, col s
            #pragma unroll
            for (int nb = 0; nb < 16; nb++) {
                uint32_t b0 = __float_as_uint(bp[nb * 8 * PAD]);
                uint32_t b1 = __float_as_uint(bp[nb * 8 * PAD + 4]);
                mma_tf32(o[nb], pa, b0, b1);
            }
        }
    }

    // ---- row denominators: reduce across the 4 lanes of each quad ----
    dsum0 += __shfl_xor_sync(0xFFFFFFFFu, dsum0, 1);
    dsum0 += __shfl_xor_sync(0xFFFFFFFFu, dsum0, 2);
    dsum1 += __shfl_xor_sync(0xFFFFFFFFu, dsum1, 1);
    dsum1 += __shfl_xor_sync(0xFFFFFFFFu, dsum1, 2);
    float inv0 = 1.0f / dsum0;
    float inv1 = 1.0f / dsum1;

    // ---- epilogue: out = O / denom ----
    float* po = out + ((size_t)bn * TSEQ + t0 + row0) * HDIM + 2 * lc;
    #pragma unroll
    for (int nb = 0; nb < 16; nb++) {
        *(float2*)(po + nb * 8)            = make_float2(o[nb][0] * inv0, o[nb][1] * inv0);
        *(float2*)(po + 8 * HDIM + nb * 8) = make_float2(o[nb][2] * inv1, o[nb][3] * inv1);
    }
}

// ============================================================================
// Launch
// ============================================================================
extern "C" void kernel_launch(void* const* d_in, const int* in_sizes, int n_in,
                              void* d_out, int out_size) {
    const float* q = (const float*)d_in[0];
    const float* k = (const float*)d_in[1];
    const float* v = (const float*)d_in[2];
    const void*  mask = d_in[3];
    float* out = (float*)d_out;

    cudaFuncSetAttribute(attn_kernel,
                         cudaFuncAttributeMaxDynamicSharedMemorySize, SMEM_BYTES);

    // Mask: detect dtype, canonicalize to uint8.
    mask_detect_kernel<<<1, 1024>>>((const uint32_t*)mask);
    mask_convert_kernel<<<(int)((MASK_ELEMS + 255) / 256), 256>>>(mask);

    // Prep: RNA-round K; transpose+RNA-round V.
    prep_k_kernel<<<(int)(BN * (size_t)SSEQ * HDIM / 4 / 256), 256>>>(k);
    vT_kernel<<<dim3(SSEQ / 32, HDIM / 32, BN), dim3(32, 8)>>>(v);

    // Main attention.
    attn_kernel<<<dim3(TSEQ / TILE, BN), 256, SMEM_BYTES>>>(q, out);
}

// round 6
// speedup vs baseline: 1.0595x; 1.0595x over previous
#include <cuda_runtime.h>
#include <cstdint>

// ============================================================================
// q[2,32,2048,128], k[2,32,2048,128], v[2,32,2048,128] fp32,
// mask[2,1,2048,2048] bool (uint8/int32/float32 auto-detected),
// out[2,32,2048,128] fp32.
// compute_103 virtual arch -> no tcgen05; tensor pipe via mma.sync tf32.
// R6: R5 pipeline with the K-tile cp.async coverage bug fixed
// (was writing only half of each 128-float K row).
// ============================================================================
#define BATCH 2
#define NHEAD 32
#define BN    64
#define TSEQ  2048
#define SSEQ  2048
#define HDIM  128
#define STILE 64
#define NSTILE 32
#define SCALE_F 0.08838834764831845f   // 1/sqrt(128)
#define KPAD  132                      // K/Q row stride (128 cols)
#define VPAD  68                       // V^T / P row stride (64 cols)

#define MASK_ELEMS ((size_t)BATCH * TSEQ * SSEQ)

// Scratch: RNA-rounded K, RNA-rounded transposed V ([bn][h][s]), canonical mask
__device__ float   g_k [(size_t)BN * SSEQ * HDIM];
__device__ float   g_vt[(size_t)BN * HDIM * SSEQ];
__device__ uint8_t g_mask[MASK_ELEMS];
__device__ int     g_mask_kind;   // 0=uint8, 1=int32, 2=float32

// ============================================================================
// helpers
// ============================================================================
__device__ __forceinline__ float rna_tf32(float x) {
    uint32_t r;
    asm("cvt.rna.tf32.f32 %0, %1;" : "=r"(r) : "f"(x));
    return __uint_as_float(r);
}
__device__ __forceinline__ uint32_t smem_to_u32(const void* p) {
    uint32_t a;
    asm("{ .reg .u64 t; cvta.to.shared.u64 t, %1; cvt.u32.u64 %0, t; }"
        : "=r"(a) : "l"(p));
    return a;
}
__device__ __forceinline__ void cp_async16(uint32_t dst, const void* src) {
    asm volatile("cp.async.cg.shared.global [%0], [%1], 16;"
                 :: "r"(dst), "l"(src) : "memory");
}
#define CP_COMMIT() asm volatile("cp.async.commit_group;" ::: "memory")
#define CP_WAIT(n)  asm volatile("cp.async.wait_group %0;" :: "n"(n) : "memory")

// D += A(16x8,row) * B(8x8,col), tf32
__device__ __forceinline__ void mma_tf32(float* d, const uint32_t* a,
                                         uint32_t b0, uint32_t b1) {
    asm volatile(
        "mma.sync.aligned.m16n8k8.row.col.f32.tf32.tf32.f32 "
        "{%0,%1,%2,%3}, {%4,%5,%6,%7}, {%8,%9}, {%0,%1,%2,%3};"
        : "+f"(d[0]), "+f"(d[1]), "+f"(d[2]), "+f"(d[3])
        : "r"(a[0]), "r"(a[1]), "r"(a[2]), "r"(a[3]), "r"(b0), "r"(b1));
}

// ============================================================================
// Mask dtype detection + canonicalization
// ============================================================================
#define DET_WORDS 65536
__global__ void mask_detect_kernel(const uint32_t* __restrict__ m) {
    __shared__ int s_not01, s_notf32;
    if (threadIdx.x == 0) { s_not01 = 0; s_notf32 = 0; }
    __syncthreads();
    int not01 = 0, notf32 = 0;
    for (int i = threadIdx.x; i < DET_WORDS; i += blockDim.x) {
        uint32_t w = m[i];
        if (w != 0u && w != 1u) not01 = 1;
        if (w != 0u && w != 0x3F800000u) notf32 = 1;
    }
    if (not01)  atomicOr(&s_not01, 1);
    if (notf32) atomicOr(&s_notf32, 1);
    __syncthreads();
    if (threadIdx.x == 0) {
        int kind;
        if (!s_not01)       kind = 1;
        else if (!s_notf32) kind = 2;
        else                kind = 0;
        g_mask_kind = kind;
    }
}

__global__ void mask_convert_kernel(const void* __restrict__ m) {
    size_t i = (size_t)blockIdx.x * blockDim.x + threadIdx.x;
    if (i >= MASK_ELEMS) return;
    int kind = g_mask_kind;
    uint8_t v;
    if (kind == 1)      v = (((const int*)m)[i] != 0) ? 1 : 0;
    else if (kind == 2) v = (((const float*)m)[i] != 0.0f) ? 1 : 0;
    else                v = (((const uint8_t*)m)[i] != 0) ? 1 : 0;
    g_mask[i] = v;
}

// ============================================================================
// Prep kernels: RNA-round K; transpose+RNA-round V
// ============================================================================
__global__ void prep_k_kernel(const float* __restrict__ k) {
    size_t i = (size_t)blockIdx.x * blockDim.x + threadIdx.x;
    float4 v = ((const float4*)k)[i];
    v.x = rna_tf32(v.x); v.y = rna_tf32(v.y);
    v.z = rna_tf32(v.z); v.w = rna_tf32(v.w);
    ((float4*)g_k)[i] = v;
}

__global__ void vT_kernel(const float* __restrict__ v) {
    __shared__ float tile[32][33];
    int bn = blockIdx.z;
    const float* vp = v + (size_t)bn * SSEQ * HDIM;
    float* vtp = g_vt + (size_t)bn * HDIM * SSEQ;
    int s0 = blockIdx.x * 32, h0 = blockIdx.y * 32;
    #pragma unroll
    for (int dy = threadIdx.y; dy < 32; dy += 8)
        tile[dy][threadIdx.x] = rna_tf32(vp[(size_t)(s0 + dy) * HDIM + h0 + threadIdx.x]);
    __syncthreads();
    #pragma unroll
    for (int dy = threadIdx.y; dy < 32; dy += 8)
        vtp[(size_t)(h0 + dy) * SSEQ + s0 + threadIdx.x] = tile[threadIdx.x][dy];
}

// ============================================================================
// Main attention kernel. Grid (TSEQ/128, BN), 256 threads, 1 CTA/SM.
// SMEM layout (floats):
//   sK[2][64][KPAD]   double-buffered K tile (rows s, cols h)
//   sV[2][128][VPAD]  double-buffered V^T tile (rows h, cols s)
//   sP[128][VPAD]     P tile (rows t, cols s)
// Q is staged through the contiguous sK pair (128 rows x KPAD), then in regs.
// ============================================================================
#define SM_K0 0
#define SM_K1 (64 * KPAD)
#define SM_V0 (2 * 64 * KPAD)
#define SM_V1 (SM_V0 + 128 * VPAD)
#define SM_P  (SM_V0 + 2 * 128 * VPAD)
#define SMEM_FLOATS (SM_P + 128 * VPAD)
#define SMEM_BYTES  (SMEM_FLOATS * 4)

__global__ void __launch_bounds__(256, 1)
attn_kernel(const float* __restrict__ q, float* __restrict__ out) {
    extern __shared__ float sm[];
    float* sP = sm + SM_P;
    const uint32_t sm_u = smem_to_u32(sm);

    const int tid = threadIdx.x;
    const int w = tid >> 5, l = tid & 31;
    const int lr = l >> 2, lc = l & 3;
    const int bn = blockIdx.y;
    const int t0 = blockIdx.x * 128;
    const int b = bn >> 5;               // NHEAD == 32
    const int row0 = w * 16 + lr;        // local row of c0/c1 (c2/c3 at +8)

    // ---- stage Q tile (scale folded + RNA) into sK pair, extract frags ----
    const float* gq = q + ((size_t)bn * TSEQ + t0) * HDIM;
    #pragma unroll
    for (int ch = 0; ch < 16; ch++) {
        int idx = tid + ch * 256;
        int r = idx >> 5, c4 = idx & 31;
        float4 v = *(const float4*)(gq + r * HDIM + c4 * 4);
        v.x = rna_tf32(v.x * SCALE_F); v.y = rna_tf32(v.y * SCALE_F);
        v.z = rna_tf32(v.z * SCALE_F); v.w = rna_tf32(v.w * SCALE_F);
        *(float4*)(sm + r * KPAD + c4 * 4) = v;
    }
    __syncthreads();

    uint32_t qa[16][4];
    #pragma unroll
    for (int kk = 0; kk < 16; kk++) {
        const float* p = sm + row0 * KPAD + kk * 8 + lc;
        qa[kk][0] = __float_as_uint(p[0]);
        qa[kk][1] = __float_as_uint(p[8 * KPAD]);
        qa[kk][2] = __float_as_uint(p[4]);
        qa[kk][3] = __float_as_uint(p[8 * KPAD + 4]);
    }
    __syncthreads();   // done reading Q staging before K tile 0 overwrites it

    float o[16][4];
    #pragma unroll
    for (int nb = 0; nb < 16; nb++) {
        o[nb][0] = 0.f; o[nb][1] = 0.f; o[nb][2] = 0.f; o[nb][3] = 0.f;
    }
    float dsum0 = 0.f, dsum1 = 0.f;

    const float* gk = g_k + (size_t)bn * SSEQ * HDIM;
    const float* gv = g_vt + (size_t)bn * HDIM * SSEQ;
    const uint8_t* gm0 = g_mask + (size_t)b * TSEQ * SSEQ
                       + (size_t)(t0 + row0) * SSEQ + 2 * lc;
    const uint8_t* gm1 = gm0 + (size_t)8 * SSEQ;

    // per-thread cp.async assignments
    const int kr = tid >> 3, kc4 = tid & 7;    // K: rows kr, kr+32; 4 f4-chunks each
    const int vr = tid >> 1, vc4 = tid & 1;    // V^T: row vr; 8 f4-chunks

    // ---- issue tile 0 ----
    {
        const float* gki = gk;
        const float* gvi = gv;
        #pragma unroll
        for (int ch = 0; ch < 2; ch++) {               // K: 64 rows x 32 f4
            int r = kr + ch * 32;
            #pragma unroll
            for (int f = 0; f < 4; f++) {
                int c4 = kc4 + f * 8;                  // f4 index 0..31
                cp_async16(sm_u + (uint32_t)(SM_K0 + r * KPAD + c4 * 4) * 4,
                           gki + (size_t)r * HDIM + c4 * 4);
            }
        }
        #pragma unroll
        for (int ch = 0; ch < 8; ch++) {               // V^T: 128 rows x 16 f4
            int c = vc4 + ch * 2;                      // f4 index 0..15
            cp_async16(sm_u + (uint32_t)(SM_V0 + vr * VPAD + c * 4) * 4,
                       gvi + (size_t)vr * SSEQ + c * 4);
        }
        CP_COMMIT();
    }

    for (int i = 0; i < NSTILE; i++) {
        const int buf = i & 1;
        const int nbuf = buf ^ 1;
        // ---- issue tile i+1 into the other buffer ----
        if (i + 1 < NSTILE) {
            const float* gki = gk + (size_t)(i + 1) * STILE * HDIM;
            const float* gvi = gv + (size_t)(i + 1) * STILE;
            const uint32_t kbase = nbuf ? SM_K1 : SM_K0;
            const uint32_t vbase = nbuf ? SM_V1 : SM_V0;
            #pragma unroll
            for (int ch = 0; ch < 2; ch++) {
                int r = kr + ch * 32;
                #pragma unroll
                for (int f = 0; f < 4; f++) {
                    int c4 = kc4 + f * 8;
                    cp_async16(sm_u + (kbase + r * KPAD + c4 * 4) * 4,
                               gki + (size_t)r * HDIM + c4 * 4);
                }
            }
            #pragma unroll
            for (int ch = 0; ch < 8; ch++) {
                int c = vc4 + ch * 2;
                cp_async16(sm_u + (vbase + vr * VPAD + c * 4) * 4,
                           gvi + (size_t)vr * SSEQ + c * 4);
            }
            CP_COMMIT();
            CP_WAIT(1);     // tile i resident; tile i+1 in flight
        } else {
            CP_WAIT(0);
        }
        __syncthreads();

        const float* sK = sm + (buf ? SM_K1 : SM_K0);
        const float* sV = sm + (buf ? SM_V1 : SM_V0);

        // ---- S = Q @ K^T : 16 kk x 8 nb ----
        float c[8][4];
        #pragma unroll
        for (int nb = 0; nb < 8; nb++) {
            c[nb][0] = 0.f; c[nb][1] = 0.f; c[nb][2] = 0.f; c[nb][3] = 0.f;
        }
        #pragma unroll
        for (int kk = 0; kk < 16; kk++) {
            const float* bp = sK + lr * KPAD + kk * 8 + lc;
            #pragma unroll
            for (int nb = 0; nb < 8; nb++) {
                uint32_t b0 = __float_as_uint(bp[nb * 8 * KPAD]);
                uint32_t b1 = __float_as_uint(bp[nb * 8 * KPAD + 4]);
                mma_tf32(c[nb], qa[kk], b0, b1);
            }
        }

        // ---- P = mask ? exp(S) : 0 ; denom ; P -> sP ----
        const uint8_t* m0p = gm0 + i * STILE;
        const uint8_t* m1p = gm1 + i * STILE;
        #pragma unroll
        for (int nb = 0; nb < 8; nb++) {
            uchar2 m0 = *(const uchar2*)(m0p + nb * 8);
            uchar2 m1 = *(const uchar2*)(m1p + nb * 8);
            float p0 = m0.x ? rna_tf32(__expf(c[nb][0])) : 0.f;
            float p1 = m0.y ? rna_tf32(__expf(c[nb][1])) : 0.f;
            float p2 = m1.x ? rna_tf32(__expf(c[nb][2])) : 0.f;
            float p3 = m1.y ? rna_tf32(__expf(c[nb][3])) : 0.f;
            dsum0 += p0 + p1;
            dsum1 += p2 + p3;
            *(float2*)(sP + row0 * VPAD + nb * 8 + 2 * lc)       = make_float2(p0, p1);
            *(float2*)(sP + (row0 + 8) * VPAD + nb * 8 + 2 * lc) = make_float2(p2, p3);
        }
        __syncwarp();   // P rows are warp-private

        // ---- O += P @ V : 8 kk x 16 nb ----
        #pragma unroll
        for (int kk = 0; kk < 8; kk++) {
            uint32_t pa[4];
            const float* pp = sP + row0 * VPAD + kk * 8 + lc;
            pa[0] = __float_as_uint(pp[0]);
            pa[1] = __float_as_uint(pp[8 * VPAD]);
            pa[2] = __float_as_uint(pp[4]);
            pa[3] = __float_as_uint(pp[8 * VPAD + 4]);
            const float* bp = sV + lr * VPAD + kk * 8 + lc;
            #pragma unroll
            for (int nb = 0; nb < 16; nb++) {
                uint32_t b0 = __float_as_uint(bp[nb * 8 * VPAD]);
                uint32_t b1 = __float_as_uint(bp[nb * 8 * VPAD + 4]);
                mma_tf32(o[nb], pa, b0, b1);
            }
        }
        __syncthreads();   // all reads of buf done before it is refilled
    }

    // ---- row denominators: reduce across the 4 lanes of each quad ----
    dsum0 += __shfl_xor_sync(0xFFFFFFFFu, dsum0, 1);
    dsum0 += __shfl_xor_sync(0xFFFFFFFFu, dsum0, 2);
    dsum1 += __shfl_xor_sync(0xFFFFFFFFu, dsum1, 1);
    dsum1 += __shfl_xor_sync(0xFFFFFFFFu, dsum1, 2);
    float inv0 = 1.0f / dsum0;
    float inv1 = 1.0f / dsum1;

    // ---- epilogue: out = O / denom ----
    float* po = out + ((size_t)bn * TSEQ + t0 + row0) * HDIM + 2 * lc;
    #pragma unroll
    for (int nb = 0; nb < 16; nb++) {
        *(float2*)(po + nb * 8)            = make_float2(o[nb][0] * inv0, o[nb][1] * inv0);
        *(float2*)(po + 8 * HDIM + nb * 8) = make_float2(o[nb][2] * inv1, o[nb][3] * inv1);
    }
}

// ============================================================================
// Launch
// ============================================================================
extern "C" void kernel_launch(void* const* d_in, const int* in_sizes, int n_in,
                              void* d_out, int out_size) {
    const float* q = (const float*)d_in[0];
    const float* k = (const float*)d_in[1];
    const float* v = (const float*)d_in[2];
    const void*  mask = d_in[3];
    float* out = (float*)d_out;

    cudaFuncSetAttribute(attn_kernel,
                         cudaFuncAttributeMaxDynamicSharedMemorySize, SMEM_BYTES);

    mask_detect_kernel<<<1, 1024>>>((const uint32_t*)mask);
    mask_convert_kernel<<<(int)((MASK_ELEMS + 255) / 256), 256>>>(mask);
    prep_k_kernel<<<(int)(BN * (size_t)SSEQ * HDIM / 4 / 256), 256>>>(k);
    vT_kernel<<<dim3(SSEQ / 32, HDIM / 32, BN), dim3(32, 8)>>>(v);

    attn_kernel<<<dim3(TSEQ / 128, BN), 256, SMEM_BYTES>>>(q, out);
}